// round 2
// baseline (speedup 1.0000x reference)
#include <cuda_runtime.h>

#define N_NODES 50000
#define N_EDGES 800000
#define NG 256

// ---------------- device scratch (no allocations allowed) ----------------
__device__ int   g_is64;
__device__ float g_PR[N_NODES * 128];   // [P | R] per node, ld=128
__device__ float g_agg[N_NODES * 64];
__device__ float g_H[N_NODES * 64];
__device__ float g_inv[N_NODES];
__device__ int   g_cnt[N_NODES];
__device__ float g_pool[NG * 64];
__device__ int   g_gcnt[NG];
__device__ float g_c0[NG * 64];
__device__ float g_t1[NG * 256];
__device__ float g_t2[NG * 128];
__device__ float g_t3[NG * 64];

// index loader that works for int32 or int64 edge/batch arrays
__device__ __forceinline__ int ld_idx(const void* p, long long i) {
    return g_is64 ? (int)((const long long*)p)[i] : ((const int*)p)[i];
}

// ---------------- dtype detection ----------------
// If data is int64 (values < 50000), every odd int32 word is 0.
// If data is int32, odd words are random edge indices (virtually never all zero).
__global__ void kdetect(const int* ei32) {
    __shared__ int any;
    if (threadIdx.x == 0) any = 0;
    __syncthreads();
    if (ei32[2 * threadIdx.x + 1] != 0) atomicExch(&any, 1);
    __syncthreads();
    if (threadIdx.x == 0) g_is64 = (any == 0) ? 1 : 0;
}

// ---------------- utility ----------------
__global__ void kzero_f(float* p, int n) {
    int i = blockIdx.x * blockDim.x + threadIdx.x;
    if (i < n) p[i] = 0.0f;
}
__global__ void kzero_i(int* p, int n) {
    int i = blockIdx.x * blockDim.x + threadIdx.x;
    if (i < n) p[i] = 0;
}

// ---------------- degree counts ----------------
__global__ void kcount(const void* ei) {
    int e = blockIdx.x * blockDim.x + threadIdx.x;
    if (e < N_EDGES) {
        int d = ld_idx(ei, (long long)N_EDGES + e);
        atomicAdd(&g_cnt[d], 1);
    }
}
__global__ void kinv() {
    int i = blockIdx.x * blockDim.x + threadIdx.x;
    if (i < N_NODES) g_inv[i] = 1.0f / fmaxf((float)g_cnt[i], 1.0f);
}

// ---------------- fused projection GEMM: PR = [X@Wl | X@Wr] ----------------
// block = 128 threads, 4 rows per block; W value reused across 4 rows.
template <int K>
__global__ void gemm_pr(const float* __restrict__ X,
                        const float* __restrict__ Wl,
                        const float* __restrict__ Wr) {
    __shared__ float xs[4][K];
    int row0 = blockIdx.x * 4;
    int tid = threadIdx.x;
#pragma unroll
    for (int r = 0; r < 4; r++)
        for (int k = tid; k < K; k += 128)
            xs[r][k] = X[(long long)(row0 + r) * K + k];
    __syncthreads();

    const float* W = (tid < 64) ? (Wl + tid) : (Wr + (tid - 64));
    float a0 = 0.f, a1 = 0.f, a2 = 0.f, a3 = 0.f;
#pragma unroll 16
    for (int k = 0; k < K; k++) {
        float w = W[k * 64];
        a0 += xs[0][k] * w;
        a1 += xs[1][k] * w;
        a2 += xs[2][k] * w;
        a3 += xs[3][k] * w;
    }
    g_PR[(long long)(row0 + 0) * 128 + tid] = a0;
    g_PR[(long long)(row0 + 1) * 128 + tid] = a1;
    g_PR[(long long)(row0 + 2) * 128 + tid] = a2;
    g_PR[(long long)(row0 + 3) * 128 + tid] = a3;
}

// ---------------- edge scatter: agg[dst] += P[src] ----------------
__global__ void kscatter(const void* ei) {
    int idx = blockIdx.x * blockDim.x + threadIdx.x;
    if (idx >= N_EDGES * 64) return;
    int e = idx >> 6;
    int c = idx & 63;
    int s = ld_idx(ei, e);
    int d = ld_idx(ei, (long long)N_EDGES + e);
    atomicAdd(&g_agg[(long long)d * 64 + c], g_PR[(long long)s * 128 + c]);
}

// ---------------- combine: H = agg*inv + bl + R ----------------
__global__ void kcombine(const float* __restrict__ bl) {
    int idx = blockIdx.x * blockDim.x + threadIdx.x;
    if (idx >= N_NODES * 64) return;
    int i = idx >> 6;
    int c = idx & 63;
    g_H[idx] = g_agg[idx] * g_inv[i] + bl[c] + g_PR[(long long)i * 128 + 64 + c];
}

// ---------------- global mean pool ----------------
__global__ void kpool(const void* batch) {
    int idx = blockIdx.x * blockDim.x + threadIdx.x;
    if (idx >= N_NODES * 64) return;
    int i = idx >> 6;
    int c = idx & 63;
    int g = ld_idx(batch, i);
    atomicAdd(&g_pool[g * 64 + c], g_H[idx]);
    if (c == 0) atomicAdd(&g_gcnt[g], 1);
}
__global__ void kpooldiv() {
    int idx = blockIdx.x * blockDim.x + threadIdx.x;
    if (idx < NG * 64) {
        int g = idx >> 6;
        g_c0[idx] = g_pool[idx] / fmaxf((float)g_gcnt[g], 1.0f);
    }
}

// ---------------- small row GEMM: Y[row] = X[row] @ W + b ----------------
__global__ void gemm_rows(const float* __restrict__ X, const float* __restrict__ W,
                          const float* __restrict__ b, float* __restrict__ Y,
                          int K, int M) {
    extern __shared__ float xs[];
    int row = blockIdx.x;
    int tid = threadIdx.x;
    for (int k = tid; k < K; k += blockDim.x) xs[k] = X[row * K + k];
    __syncthreads();
    if (tid < M) {
        float acc = b[tid];
        for (int k = 0; k < K; k++) acc += xs[k] * W[k * M + tid];
        Y[row * M + tid] = acc;
    }
}

// ---------------- batchnorm (training mode, biased var) + tanh, in place ----------------
// grid = M columns, block = 256 (= NUM_GRAPHS rows)
__global__ void bn_tanh(float* X, const float* __restrict__ g,
                        const float* __restrict__ be, int M) {
    int c = blockIdx.x;
    int r = threadIdx.x;
    __shared__ float red[256];
    __shared__ float stat;
    float v = X[r * M + c];
    red[r] = v;
    __syncthreads();
    for (int s = 128; s > 0; s >>= 1) {
        if (r < s) red[r] += red[r + s];
        __syncthreads();
    }
    if (r == 0) stat = red[0] * (1.0f / 256.0f);
    __syncthreads();
    float mean = stat;
    float d = v - mean;
    __syncthreads();
    red[r] = d * d;
    __syncthreads();
    for (int s = 128; s > 0; s >>= 1) {
        if (r < s) red[r] += red[r + s];
        __syncthreads();
    }
    if (r == 0) stat = rsqrtf(red[0] * (1.0f / 256.0f) + 1e-5f);
    __syncthreads();
    X[r * M + c] = tanhf(d * stat * g[c] + be[c]);
}

// ---------------- host launch ----------------
extern "C" void kernel_launch(void* const* d_in, const int* in_sizes, int n_in,
                              void* d_out, int out_size) {
    const float* x      = (const float*)d_in[0];
    const void*  ei     = d_in[1];
    const void*  batch  = d_in[2];
    const float* W1l    = (const float*)d_in[3];
    const float* b1l    = (const float*)d_in[4];
    const float* W1r    = (const float*)d_in[5];
    const float* W2l    = (const float*)d_in[6];
    const float* b2l    = (const float*)d_in[7];
    const float* W2r    = (const float*)d_in[8];
    const float* W3l    = (const float*)d_in[9];
    const float* b3l    = (const float*)d_in[10];
    const float* W3r    = (const float*)d_in[11];
    const float* lin1_w = (const float*)d_in[12];
    const float* lin1_b = (const float*)d_in[13];
    const float* g1     = (const float*)d_in[14];
    const float* be1    = (const float*)d_in[15];
    const float* lin2_w = (const float*)d_in[16];
    const float* lin2_b = (const float*)d_in[17];
    const float* g2     = (const float*)d_in[18];
    const float* be2    = (const float*)d_in[19];
    const float* lin3_w = (const float*)d_in[20];
    const float* lin3_b = (const float*)d_in[21];
    const float* g3     = (const float*)d_in[22];
    const float* be3    = (const float*)d_in[23];
    const float* lin4_w = (const float*)d_in[24];
    const float* lin4_b = (const float*)d_in[25];
    float* out = (float*)d_out;

    void* pv;
    cudaGetSymbolAddress(&pv, g_cnt);  int*   cnt  = (int*)pv;
    cudaGetSymbolAddress(&pv, g_agg);  float* agg  = (float*)pv;
    cudaGetSymbolAddress(&pv, g_H);    float* H    = (float*)pv;
    cudaGetSymbolAddress(&pv, g_pool); float* pool = (float*)pv;
    cudaGetSymbolAddress(&pv, g_gcnt); int*   gcnt = (int*)pv;
    cudaGetSymbolAddress(&pv, g_c0);   float* c0   = (float*)pv;
    cudaGetSymbolAddress(&pv, g_t1);   float* t1   = (float*)pv;
    cudaGetSymbolAddress(&pv, g_t2);   float* t2   = (float*)pv;
    cudaGetSymbolAddress(&pv, g_t3);   float* t3   = (float*)pv;

    const int NB_NODE = N_NODES / 4;       // 12500 blocks for gemm_pr
    const int NV      = N_NODES * 64;      // 3.2M
    const int NE64    = N_EDGES * 64;      // 51.2M

    kdetect<<<1, 128>>>((const int*)ei);

    // degree counts -> inverse
    kzero_i<<<(N_NODES + 255) / 256, 256>>>(cnt, N_NODES);
    kcount<<<(N_EDGES + 255) / 256, 256>>>(ei);
    kinv<<<(N_NODES + 255) / 256, 256>>>();

    // ---- SAGE layer 1 (K=128) ----
    gemm_pr<128><<<NB_NODE, 128>>>(x, W1l, W1r);
    kzero_f<<<(NV + 255) / 256, 256>>>(agg, NV);
    kscatter<<<(NE64 + 255) / 256, 256>>>(ei);
    kcombine<<<(NV + 255) / 256, 256>>>(b1l);

    // ---- SAGE layer 2 (K=64) ----
    gemm_pr<64><<<NB_NODE, 128>>>(H, W2l, W2r);
    kzero_f<<<(NV + 255) / 256, 256>>>(agg, NV);
    kscatter<<<(NE64 + 255) / 256, 256>>>(ei);
    kcombine<<<(NV + 255) / 256, 256>>>(b2l);

    // ---- SAGE layer 3 (K=64) ----
    gemm_pr<64><<<NB_NODE, 128>>>(H, W3l, W3r);
    kzero_f<<<(NV + 255) / 256, 256>>>(agg, NV);
    kscatter<<<(NE64 + 255) / 256, 256>>>(ei);
    kcombine<<<(NV + 255) / 256, 256>>>(b3l);

    // ---- global mean pool ----
    kzero_f<<<(NG * 64 + 255) / 256, 256>>>(pool, NG * 64);
    kzero_i<<<1, 256>>>(gcnt, NG);
    kpool<<<(NV + 255) / 256, 256>>>(batch);
    kpooldiv<<<(NG * 64) / 256, 256>>>();

    // ---- MLP head ----
    gemm_rows<<<NG, 256, 256 * 4>>>(c0, lin1_w, lin1_b, t1, 64, 256);
    bn_tanh<<<256, 256>>>(t1, g1, be1, 256);
    gemm_rows<<<NG, 128, 256 * 4>>>(t1, lin2_w, lin2_b, t2, 256, 128);
    bn_tanh<<<128, 256>>>(t2, g2, be2, 128);
    gemm_rows<<<NG, 64, 128 * 4>>>(t2, lin3_w, lin3_b, t3, 128, 64);
    bn_tanh<<<64, 256>>>(t3, g3, be3, 64);
    gemm_rows<<<NG, 32, 64 * 4>>>(t3, lin4_w, lin4_b, out, 64, 10);
}

// round 3
// speedup vs baseline: 1.0093x; 1.0093x over previous
#include <cuda_runtime.h>

#define N_NODES 50000
#define N_EDGES 800000
#define NG 256

// ---------------- device scratch (no allocations allowed) ----------------
__device__ int   g_is64;
__device__ float g_PR[N_NODES * 128];   // [P | R] per node, ld=128
__device__ float g_agg[N_NODES * 64];
__device__ float g_H[N_NODES * 64];
__device__ float g_inv[N_NODES];
__device__ int   g_cnt[N_NODES];
__device__ float g_pool[NG * 64];
__device__ int   g_gcnt[NG];
__device__ float g_c0[NG * 64];
__device__ float g_t1[NG * 256];
__device__ float g_t2[NG * 128];
__device__ float g_t3[NG * 64];

// index loader that works for int32 or int64 edge/batch arrays
__device__ __forceinline__ int ld_idx(const void* p, long long i) {
    return g_is64 ? (int)((const long long*)p)[i] : ((const int*)p)[i];
}

// ---------------- dtype detection ----------------
// If data is int64 (values < 50000), every odd int32 word is 0.
// If data is int32, odd words are random edge indices (virtually never all zero).
__global__ void kdetect(const int* ei32) {
    __shared__ int any;
    if (threadIdx.x == 0) any = 0;
    __syncthreads();
    if (ei32[2 * threadIdx.x + 1] != 0) atomicExch(&any, 1);
    __syncthreads();
    if (threadIdx.x == 0) g_is64 = (any == 0) ? 1 : 0;
}

// ---------------- utility ----------------
__global__ void kzero_f(float* p, int n) {
    int i = blockIdx.x * blockDim.x + threadIdx.x;
    if (i < n) p[i] = 0.0f;
}
__global__ void kzero_i(int* p, int n) {
    int i = blockIdx.x * blockDim.x + threadIdx.x;
    if (i < n) p[i] = 0;
}

// ---------------- degree counts ----------------
__global__ void kcount(const void* ei) {
    int e = blockIdx.x * blockDim.x + threadIdx.x;
    if (e < N_EDGES) {
        int d = ld_idx(ei, (long long)N_EDGES + e);
        atomicAdd(&g_cnt[d], 1);
    }
}
__global__ void kinv() {
    int i = blockIdx.x * blockDim.x + threadIdx.x;
    if (i < N_NODES) g_inv[i] = 1.0f / fmaxf((float)g_cnt[i], 1.0f);
}

// ---------------- fused projection GEMM: PR = [X@Wl | X@Wr] ----------------
// block = 128 threads, 4 rows per block; W value reused across 4 rows.
template <int K>
__global__ void gemm_pr(const float* __restrict__ X,
                        const float* __restrict__ Wl,
                        const float* __restrict__ Wr) {
    __shared__ float xs[4][K];
    int row0 = blockIdx.x * 4;
    int tid = threadIdx.x;
#pragma unroll
    for (int r = 0; r < 4; r++)
        for (int k = tid; k < K; k += 128)
            xs[r][k] = X[(long long)(row0 + r) * K + k];
    __syncthreads();

    const float* W = (tid < 64) ? (Wl + tid) : (Wr + (tid - 64));
    float a0 = 0.f, a1 = 0.f, a2 = 0.f, a3 = 0.f;
#pragma unroll 16
    for (int k = 0; k < K; k++) {
        float w = W[k * 64];
        a0 += xs[0][k] * w;
        a1 += xs[1][k] * w;
        a2 += xs[2][k] * w;
        a3 += xs[3][k] * w;
    }
    g_PR[(long long)(row0 + 0) * 128 + tid] = a0;
    g_PR[(long long)(row0 + 1) * 128 + tid] = a1;
    g_PR[(long long)(row0 + 2) * 128 + tid] = a2;
    g_PR[(long long)(row0 + 3) * 128 + tid] = a3;
}

// ---------------- edge scatter: agg[dst] += P[src] ----------------
__global__ void kscatter(const void* ei) {
    int idx = blockIdx.x * blockDim.x + threadIdx.x;
    if (idx >= N_EDGES * 64) return;
    int e = idx >> 6;
    int c = idx & 63;
    int s = ld_idx(ei, e);
    int d = ld_idx(ei, (long long)N_EDGES + e);
    atomicAdd(&g_agg[(long long)d * 64 + c], g_PR[(long long)s * 128 + c]);
}

// ---------------- combine: H = agg*inv + bl + R ----------------
__global__ void kcombine(const float* __restrict__ bl) {
    int idx = blockIdx.x * blockDim.x + threadIdx.x;
    if (idx >= N_NODES * 64) return;
    int i = idx >> 6;
    int c = idx & 63;
    g_H[idx] = g_agg[idx] * g_inv[i] + bl[c] + g_PR[(long long)i * 128 + 64 + c];
}

// ---------------- global mean pool ----------------
__global__ void kpool(const void* batch) {
    int idx = blockIdx.x * blockDim.x + threadIdx.x;
    if (idx >= N_NODES * 64) return;
    int i = idx >> 6;
    int c = idx & 63;
    int g = ld_idx(batch, i);
    atomicAdd(&g_pool[g * 64 + c], g_H[idx]);
    if (c == 0) atomicAdd(&g_gcnt[g], 1);
}
__global__ void kpooldiv() {
    int idx = blockIdx.x * blockDim.x + threadIdx.x;
    if (idx < NG * 64) {
        int g = idx >> 6;
        g_c0[idx] = g_pool[idx] / fmaxf((float)g_gcnt[g], 1.0f);
    }
}

// ---------------- small row GEMM: Y[row] = X[row] @ W + b ----------------
__global__ void gemm_rows(const float* __restrict__ X, const float* __restrict__ W,
                          const float* __restrict__ b, float* __restrict__ Y,
                          int K, int M) {
    extern __shared__ float xs[];
    int row = blockIdx.x;
    int tid = threadIdx.x;
    for (int k = tid; k < K; k += blockDim.x) xs[k] = X[row * K + k];
    __syncthreads();
    if (tid < M) {
        float acc = b[tid];
        for (int k = 0; k < K; k++) acc += xs[k] * W[k * M + tid];
        Y[row * M + tid] = acc;
    }
}

// ---------------- batchnorm (training mode, biased var) + tanh, in place ----------------
// grid = M columns, block = 256 (= NUM_GRAPHS rows)
__global__ void bn_tanh(float* X, const float* __restrict__ g,
                        const float* __restrict__ be, int M) {
    int c = blockIdx.x;
    int r = threadIdx.x;
    __shared__ float red[256];
    __shared__ float stat;
    float v = X[r * M + c];
    red[r] = v;
    __syncthreads();
    for (int s = 128; s > 0; s >>= 1) {
        if (r < s) red[r] += red[r + s];
        __syncthreads();
    }
    if (r == 0) stat = red[0] * (1.0f / 256.0f);
    __syncthreads();
    float mean = stat;
    float d = v - mean;
    __syncthreads();
    red[r] = d * d;
    __syncthreads();
    for (int s = 128; s > 0; s >>= 1) {
        if (r < s) red[r] += red[r + s];
        __syncthreads();
    }
    if (r == 0) stat = rsqrtf(red[0] * (1.0f / 256.0f) + 1e-5f);
    __syncthreads();
    X[r * M + c] = tanhf(d * stat * g[c] + be[c]);
}

// ---------------- host launch ----------------
extern "C" void kernel_launch(void* const* d_in, const int* in_sizes, int n_in,
                              void* d_out, int out_size) {
    const float* x      = (const float*)d_in[0];
    const void*  ei     = d_in[1];
    const void*  batch  = d_in[2];
    const float* W1l    = (const float*)d_in[3];
    const float* b1l    = (const float*)d_in[4];
    const float* W1r    = (const float*)d_in[5];
    const float* W2l    = (const float*)d_in[6];
    const float* b2l    = (const float*)d_in[7];
    const float* W2r    = (const float*)d_in[8];
    const float* W3l    = (const float*)d_in[9];
    const float* b3l    = (const float*)d_in[10];
    const float* W3r    = (const float*)d_in[11];
    const float* lin1_w = (const float*)d_in[12];
    const float* lin1_b = (const float*)d_in[13];
    const float* g1     = (const float*)d_in[14];
    const float* be1    = (const float*)d_in[15];
    const float* lin2_w = (const float*)d_in[16];
    const float* lin2_b = (const float*)d_in[17];
    const float* g2     = (const float*)d_in[18];
    const float* be2    = (const float*)d_in[19];
    const float* lin3_w = (const float*)d_in[20];
    const float* lin3_b = (const float*)d_in[21];
    const float* g3     = (const float*)d_in[22];
    const float* be3    = (const float*)d_in[23];
    const float* lin4_w = (const float*)d_in[24];
    const float* lin4_b = (const float*)d_in[25];
    float* out = (float*)d_out;

    void* pv;
    cudaGetSymbolAddress(&pv, g_cnt);  int*   cnt  = (int*)pv;
    cudaGetSymbolAddress(&pv, g_agg);  float* agg  = (float*)pv;
    cudaGetSymbolAddress(&pv, g_H);    float* H    = (float*)pv;
    cudaGetSymbolAddress(&pv, g_pool); float* pool = (float*)pv;
    cudaGetSymbolAddress(&pv, g_gcnt); int*   gcnt = (int*)pv;
    cudaGetSymbolAddress(&pv, g_c0);   float* c0   = (float*)pv;
    cudaGetSymbolAddress(&pv, g_t1);   float* t1   = (float*)pv;
    cudaGetSymbolAddress(&pv, g_t2);   float* t2   = (float*)pv;
    cudaGetSymbolAddress(&pv, g_t3);   float* t3   = (float*)pv;

    const int NB_NODE = N_NODES / 4;       // 12500 blocks for gemm_pr
    const int NV      = N_NODES * 64;      // 3.2M
    const int NE64    = N_EDGES * 64;      // 51.2M

    kdetect<<<1, 128>>>((const int*)ei);

    // degree counts -> inverse
    kzero_i<<<(N_NODES + 255) / 256, 256>>>(cnt, N_NODES);
    kcount<<<(N_EDGES + 255) / 256, 256>>>(ei);
    kinv<<<(N_NODES + 255) / 256, 256>>>();

    // ---- SAGE layer 1 (K=128) ----
    gemm_pr<128><<<NB_NODE, 128>>>(x, W1l, W1r);
    kzero_f<<<(NV + 255) / 256, 256>>>(agg, NV);
    kscatter<<<(NE64 + 255) / 256, 256>>>(ei);
    kcombine<<<(NV + 255) / 256, 256>>>(b1l);

    // ---- SAGE layer 2 (K=64) ----
    gemm_pr<64><<<NB_NODE, 128>>>(H, W2l, W2r);
    kzero_f<<<(NV + 255) / 256, 256>>>(agg, NV);
    kscatter<<<(NE64 + 255) / 256, 256>>>(ei);
    kcombine<<<(NV + 255) / 256, 256>>>(b2l);

    // ---- SAGE layer 3 (K=64) ----
    gemm_pr<64><<<NB_NODE, 128>>>(H, W3l, W3r);
    kzero_f<<<(NV + 255) / 256, 256>>>(agg, NV);
    kscatter<<<(NE64 + 255) / 256, 256>>>(ei);
    kcombine<<<(NV + 255) / 256, 256>>>(b3l);

    // ---- global mean pool ----
    kzero_f<<<(NG * 64 + 255) / 256, 256>>>(pool, NG * 64);
    kzero_i<<<1, 256>>>(gcnt, NG);
    kpool<<<(NV + 255) / 256, 256>>>(batch);
    kpooldiv<<<(NG * 64) / 256, 256>>>();

    // ---- MLP head ----
    gemm_rows<<<NG, 256, 256 * 4>>>(c0, lin1_w, lin1_b, t1, 64, 256);
    bn_tanh<<<256, 256>>>(t1, g1, be1, 256);
    gemm_rows<<<NG, 128, 256 * 4>>>(t1, lin2_w, lin2_b, t2, 256, 128);
    bn_tanh<<<128, 256>>>(t2, g2, be2, 128);
    gemm_rows<<<NG, 64, 128 * 4>>>(t2, lin3_w, lin3_b, t3, 128, 64);
    bn_tanh<<<64, 256>>>(t3, g3, be3, 64);
    gemm_rows<<<NG, 32, 64 * 4>>>(t3, lin4_w, lin4_b, out, 64, 10);
}